// round 8
// baseline (speedup 1.0000x reference)
#include <cuda_runtime.h>
#include <cuda_fp16.h>
#include <math.h>
#include <stdint.h>

// ---------------- packed fp16 weights ----------------
// g_w2: [m4][nh2][kc16][n256][k32] = 1,048,576 halves (2MB)
// g_w1: [m4][n512][k16]  (k10 = b1) = 32,768 halves
// g_hd: [m4][n32][k512]  (n: 0-2 pos, 3-11 coef, 12-20 cov, 21 attn, 22-31 zero)
__device__ __align__(16) __half g_w2[1048576];
__device__ __align__(16) __half g_w1[32768];
__device__ __align__(16) __half g_hd[65536];
// head partials: [g*2+nh (18)][sample (32768)][22] f32
__device__ float g_part[18 * 32768 * 22];

struct PM {
  const float *tokens;
  const float *ent_b2, *pad_b2;
};
struct PE {
  const float *tokens;
  const float *ent_bpos, *ent_bc, *ent_bv;
  const float *b_bpos, *b_bc, *b_bv;
  const float *gs_W, *gs_b;
  float *out;
};

__global__ void pack_kernel(const float* eW2, const float* pW2,
                            const float* eW1, const float* eb1,
                            const float* pW1, const float* pb1,
                            const float* eWpos, const float* eWc, const float* eWv,
                            const float* bWpos, const float* bWc, const float* bWv,
                            const float* attnW) {
  int tid = blockIdx.x * blockDim.x + threadIdx.x;
  int NT = gridDim.x * blockDim.x;
  for (int idx = tid; idx < 4 * 512 * 512; idx += NT) {
    int m = idx >> 18, r = idx & 262143, k = r >> 9, n = r & 511;
    float v = (m < 3) ? eW2[m * 262144 + k * 512 + n] : pW2[k * 512 + n];
    int dst = ((m * 2 + (n >> 8)) * 16 + (k >> 5)) * 8192 + (n & 255) * 32 + (k & 31);
    g_w2[dst] = __float2half(v);
  }
  for (int idx = tid; idx < 4 * 512 * 16; idx += NT) {
    int m = idx >> 13, r = idx & 8191, n = r >> 4, k = r & 15;
    float v = 0.f;
    if (k < 10)       v = (m < 3) ? eW1[m * 5120 + k * 512 + n] : pW1[k * 512 + n];
    else if (k == 10) v = (m < 3) ? eb1[m * 512 + n] : pb1[n];
    g_w1[(m * 512 + n) * 16 + k] = __float2half(v);
  }
  for (int idx = tid; idx < 4 * 32 * 512; idx += NT) {
    int m = idx >> 14, r = idx & 16383, n = r >> 9, k = r & 511;
    float v = 0.f;
    if (m < 3) {
      if (n < 3)       v = eWpos[m * 1536 + k * 3 + n];
      else if (n < 12) v = eWc[m * 4608 + k * 9 + (n - 3)];
      else if (n < 21) v = eWv[m * 4608 + k * 9 + (n - 12)];
    } else {
      if (n < 3)       v = bWpos[k * 3 + n];
      else if (n < 12) v = bWc[k * 9 + (n - 3)];
      else if (n < 21) v = bWv[k * 9 + (n - 12)];
      else if (n == 21) v = attnW[k];
    }
    g_hd[(m * 32 + n) * 512 + k] = __float2half(v);
  }
}

// ---------------- mma helpers ----------------
__device__ __forceinline__ void ldsm4(uint32_t a, uint32_t& r0, uint32_t& r1,
                                      uint32_t& r2, uint32_t& r3) {
  asm volatile("ldmatrix.sync.aligned.m8n8.x4.shared.b16 {%0,%1,%2,%3}, [%4];"
               : "=r"(r0), "=r"(r1), "=r"(r2), "=r"(r3) : "r"(a));
}
__device__ __forceinline__ void mma16816(float* c, uint32_t a0, uint32_t a1,
                                         uint32_t a2, uint32_t a3,
                                         uint32_t b0, uint32_t b1) {
  asm volatile(
      "mma.sync.aligned.m16n8k16.row.col.f32.f16.f16.f32 "
      "{%0,%1,%2,%3},{%4,%5,%6,%7},{%8,%9},{%0,%1,%2,%3};"
      : "+f"(c[0]), "+f"(c[1]), "+f"(c[2]), "+f"(c[3])
      : "r"(a0), "r"(a1), "r"(a2), "r"(a3), "r"(b0), "r"(b1));
}
#define CP16(dst, src) asm volatile("cp.async.ca.shared.global [%0], [%1], 16;" :: "r"(dst), "l"(src))
#define CPCOMMIT() asm volatile("cp.async.commit_group;" ::: "memory")
#define CPWAIT2() asm volatile("cp.async.wait_group 2;" ::: "memory")

__device__ __forceinline__ uint32_t packrelu(float a, float b) {
  __half2 h = __floats2half2_rn(fmaxf(a, 0.f), fmaxf(b, 0.f));
  return *(uint32_t*)&h;
}

// ---------------- smem layout (bytes) ----------------
#define NTH 512
static constexpr int OF_A  = 0;        // A/h1/h2 tile: 128 rows x 1040B (520 halves)
static constexpr int OF_R  = 133120;   // 4-stage ring, 4 x 20480 (256 rows x 80B); W1 parks here in prologue
static constexpr int OF_XT = 215040;   // x-tile 128 rows x 32B = 4096
static constexpr int OF_P  = 219136;   // s_part 128 x 24 f32 = 12288
static constexpr int SMEM_SZ = 231424; // fits 232,448 limit, 1 CTA/SM

__device__ __forceinline__ float softplusf(float x) { return (x > 20.f) ? x : log1pf(expf(x)); }

__global__ void __launch_bounds__(NTH, 1) spectral_mma_kernel(PM p) {
  extern __shared__ __align__(128) unsigned char sm[];
  const uint32_t smb = (uint32_t)__cvta_generic_to_shared(sm);
  const int t = threadIdx.x, wid = t >> 5, lane = t & 31;
  const int g = blockIdx.y >> 1, nh = blockIdx.y & 1;
  const int m = (g < 3) ? g : 3;
  const int s0 = blockIdx.x * 128;
  const int mw = wid & 3, nw = wid >> 2;                // 4 M-warps x 4 N-warps (128 x 256)
  const int ag_r = ((lane >> 3) & 1) * 8 + (lane & 7);  // A ldsm: row offset
  const int ag_k = ((lane >> 4) & 1) * 8;               // A ldsm: k offset
  const int bg_n = ((lane >> 4) & 1) * 8 + (lane & 7);  // B ldsm: n offset
  const int bg_k = ((lane >> 3) & 1) * 8;               // B ldsm: k offset
  const int lr = lane >> 2, lc2 = (lane & 3) * 2;       // C frag mapping

  // ---- prologue: zero s_part, build x-tile, park W1 in ring ----
  for (int i = t; i < 128 * 24; i += NTH) ((float*)(sm + OF_P))[i] = 0.f;
  for (int i = t; i < 128 * 16; i += NTH) {
    int s = i >> 4, k = i & 15;
    float v = (k < 10) ? p.tokens[(size_t)(s0 + s) * 100 + g * 10 + k] : (k == 10 ? 1.f : 0.f);
    *(__half*)(sm + OF_XT + s * 32 + k * 2) = __float2half(v);
  }
  for (int u = t; u < 1024; u += NTH)    // W1T: 512 rows x 32B data, 48B stride
    *(uint4*)(sm + OF_R + (u >> 1) * 48 + (u & 1) * 16) =
        *(const uint4*)((const char*)g_w1 + m * 16384 + u * 16);
  __syncthreads();

  // ---- phase A: h1 = relu(x @ W1T) -> A-tile, two 256-col passes ----
  {
    uint32_t xa[2][4];
    ldsm4(smb + OF_XT + (mw * 32 + ag_r) * 32 + ag_k * 2, xa[0][0], xa[0][1], xa[0][2], xa[0][3]);
    ldsm4(smb + OF_XT + (mw * 32 + 16 + ag_r) * 32 + ag_k * 2, xa[1][0], xa[1][1], xa[1][2], xa[1][3]);
#pragma unroll
    for (int pss = 0; pss < 2; ++pss) {
#pragma unroll
      for (int pq = 0; pq < 4; ++pq) {
        uint32_t b[4];
        int nr = pss * 256 + nw * 64 + pq * 16 + bg_n;
        ldsm4(smb + OF_R + nr * 48 + bg_k * 2, b[0], b[1], b[2], b[3]);
        float pa[2][2][4];
#pragma unroll
        for (int mt = 0; mt < 2; ++mt)
#pragma unroll
          for (int tn = 0; tn < 2; ++tn) {
#pragma unroll
            for (int i = 0; i < 4; ++i) pa[mt][tn][i] = 0.f;
            mma16816(pa[mt][tn], xa[mt][0], xa[mt][1], xa[mt][2], xa[mt][3],
                     b[tn * 2], b[tn * 2 + 1]);
          }
#pragma unroll
        for (int mt = 0; mt < 2; ++mt)
#pragma unroll
          for (int tn = 0; tn < 2; ++tn) {
            int col = pss * 256 + nw * 64 + pq * 16 + tn * 8 + lc2;
            int row0 = mw * 32 + mt * 16 + lr;
            *(__half2*)(sm + OF_A + row0 * 1040 + col * 2) =
                __floats2half2_rn(fmaxf(pa[mt][tn][0], 0.f), fmaxf(pa[mt][tn][1], 0.f));
            *(__half2*)(sm + OF_A + (row0 + 8) * 1040 + col * 2) =
                __floats2half2_rn(fmaxf(pa[mt][tn][2], 0.f), fmaxf(pa[mt][tn][3], 0.f));
          }
      }
    }
  }
  __syncthreads();   // h1 complete; ring (W1) now free

  // ---- cp.async prologue: chunks 0..2 into stages 0..2 ----
  const char* w2base = (const char*)g_w2 + (size_t)(m * 2 + nh) * 262144;
#pragma unroll
  for (int st = 0; st < 3; ++st) {
    const char* src = w2base + st * 16384;
    for (int u = t; u < 1024; u += NTH)
      CP16(smb + OF_R + st * 20480 + (u >> 2) * 80 + (u & 3) * 16, src + u * 16);
    CPCOMMIT();
  }

  float acc[2][8][4];
#pragma unroll
  for (int mt = 0; mt < 2; ++mt)
#pragma unroll
    for (int nt = 0; nt < 8; ++nt)
#pragma unroll
      for (int i = 0; i < 4; ++i) acc[mt][nt][i] = 0.f;

  // ---- GEMM1 mainloop: 16 k32 chunks, 4-stage ring ----
  for (int kc = 0; kc < 16; ++kc) {
    CPWAIT2();
    __syncthreads();
    if (kc < 13) {
      int st = (kc + 3) & 3;
      const char* src = w2base + (kc + 3) * 16384;
      for (int u = t; u < 1024; u += NTH)
        CP16(smb + OF_R + st * 20480 + (u >> 2) * 80 + (u & 3) * 16, src + u * 16);
      CPCOMMIT();
    }
    uint32_t bo = smb + OF_R + (kc & 3) * 20480;
#pragma unroll
    for (int kt = 0; kt < 2; ++kt) {
      int ak = kc * 32 + kt * 16;
      uint32_t A0[4], A1[4];
      ldsm4(smb + OF_A + (mw * 32 + ag_r) * 1040 + (ak + ag_k) * 2, A0[0], A0[1], A0[2], A0[3]);
      ldsm4(smb + OF_A + (mw * 32 + 16 + ag_r) * 1040 + (ak + ag_k) * 2, A1[0], A1[1], A1[2], A1[3]);
#pragma unroll
      for (int pq = 0; pq < 4; ++pq) {
        uint32_t b[4];
        ldsm4(bo + (nw * 64 + pq * 16 + bg_n) * 80 + (kt * 16 + bg_k) * 2,
              b[0], b[1], b[2], b[3]);
        mma16816(acc[0][pq * 2],     A0[0], A0[1], A0[2], A0[3], b[0], b[1]);
        mma16816(acc[0][pq * 2 + 1], A0[0], A0[1], A0[2], A0[3], b[2], b[3]);
        mma16816(acc[1][pq * 2],     A1[0], A1[1], A1[2], A1[3], b[0], b[1]);
        mma16816(acc[1][pq * 2 + 1], A1[0], A1[1], A1[2], A1[3], b[2], b[3]);
      }
    }
  }
  __syncthreads();   // all ring reads done

  // ---- h2 (bias+relu) -> A-tile cols 0..255 (overwrite) ----
  {
    const float* b2 = (g < 3) ? (p.ent_b2 + m * 512) : p.pad_b2;
#pragma unroll
    for (int mt = 0; mt < 2; ++mt)
#pragma unroll
      for (int nt = 0; nt < 8; ++nt) {
        int lcol = nw * 64 + nt * 8 + lc2;
        float bb0 = __ldg(b2 + nh * 256 + lcol), bb1 = __ldg(b2 + nh * 256 + lcol + 1);
        int row0 = mw * 32 + mt * 16 + lr;
        *(__half2*)(sm + OF_A + row0 * 1040 + lcol * 2) =
            __floats2half2_rn(fmaxf(acc[mt][nt][0] + bb0, 0.f), fmaxf(acc[mt][nt][1] + bb1, 0.f));
        *(__half2*)(sm + OF_A + (row0 + 8) * 1040 + lcol * 2) =
            __floats2half2_rn(fmaxf(acc[mt][nt][2] + bb0, 0.f), fmaxf(acc[mt][nt][3] + bb1, 0.f));
      }
  }
  // ---- copy Whd k-half slice (32 n x 256 k), stride 528B, into ring ----
  for (int u = t; u < 1024; u += NTH)
    *(uint4*)(sm + OF_R + (u >> 5) * 528 + (u & 31) * 16) =
        *(const uint4*)(g_hd + (size_t)(m * 32 + (u >> 5)) * 512 + nh * 256 + (u & 31) * 8);
  __syncthreads();

  // ---- heads GEMM: warp = (row strip mw) x (k-slice nw of 64), n=24 ----
  {
    float hacc[2][3][4];
#pragma unroll
    for (int mt = 0; mt < 2; ++mt)
#pragma unroll
      for (int nt = 0; nt < 3; ++nt)
#pragma unroll
        for (int i = 0; i < 4; ++i) hacc[mt][nt][i] = 0.f;
#pragma unroll
    for (int q = 0; q < 4; ++q) {
      int koff = nw * 64 + q * 16;
      uint32_t A0[4], A1[4], b0[4], b1[4];
      ldsm4(smb + OF_A + (mw * 32 + ag_r) * 1040 + (koff + ag_k) * 2, A0[0], A0[1], A0[2], A0[3]);
      ldsm4(smb + OF_A + (mw * 32 + 16 + ag_r) * 1040 + (koff + ag_k) * 2, A1[0], A1[1], A1[2], A1[3]);
      ldsm4(smb + OF_R + bg_n * 528 + (koff + bg_k) * 2, b0[0], b0[1], b0[2], b0[3]);
      ldsm4(smb + OF_R + (16 + bg_n) * 528 + (koff + bg_k) * 2, b1[0], b1[1], b1[2], b1[3]);
      mma16816(hacc[0][0], A0[0], A0[1], A0[2], A0[3], b0[0], b0[1]);
      mma16816(hacc[0][1], A0[0], A0[1], A0[2], A0[3], b0[2], b0[3]);
      mma16816(hacc[0][2], A0[0], A0[1], A0[2], A0[3], b1[0], b1[1]);
      mma16816(hacc[1][0], A1[0], A1[1], A1[2], A1[3], b0[0], b0[1]);
      mma16816(hacc[1][1], A1[0], A1[1], A1[2], A1[3], b0[2], b0[3]);
      mma16816(hacc[1][2], A1[0], A1[1], A1[2], A1[3], b1[0], b1[1]);
    }
    float* sp = (float*)(sm + OF_P);
#pragma unroll
    for (int mt = 0; mt < 2; ++mt)
#pragma unroll
      for (int nt = 0; nt < 3; ++nt) {
        int row0 = mw * 32 + mt * 16 + lr, col = nt * 8 + lc2;
        atomicAdd(sp + row0 * 24 + col,           hacc[mt][nt][0]);
        atomicAdd(sp + row0 * 24 + col + 1,       hacc[mt][nt][1]);
        atomicAdd(sp + (row0 + 8) * 24 + col,     hacc[mt][nt][2]);
        atomicAdd(sp + (row0 + 8) * 24 + col + 1, hacc[mt][nt][3]);
      }
  }
  __syncthreads();

  for (int i = t; i < 128 * 22; i += NTH) {
    int s = i / 22, c = i - s * 22;
    g_part[((size_t)(g * 2 + nh) * 32768 + s0 + s) * 22 + c] = ((float*)(sm + OF_P))[s * 24 + c];
  }
}

__global__ void epilogue_kernel(PE p, int B) {
  int s = blockIdx.x * blockDim.x + threadIdx.x;
  if (s >= B) return;
  float hd[9][22];
#pragma unroll
  for (int q = 0; q < 9; ++q) {
    const float* p0 = g_part + ((size_t)(q * 2) * 32768 + s) * 22;
    const float* p1 = g_part + ((size_t)(q * 2 + 1) * 32768 + s) * 22;
#pragma unroll
    for (int c = 0; c < 22; ++c) hd[q][c] = p0[c] + p1[c];
  }
  float mx = -1e30f;
#pragma unroll
  for (int q = 3; q < 9; ++q) mx = fmaxf(mx, hd[q][21]);
  float den = 0.f, agg[21];
#pragma unroll
  for (int c = 0; c < 21; ++c) agg[c] = 0.f;
#pragma unroll
  for (int q = 3; q < 9; ++q) {
    float w = expf(hd[q][21] - mx);
    den += w;
#pragma unroll
    for (int c = 0; c < 21; ++c) agg[c] = fmaf(w, hd[q][c], agg[c]);
  }
  float inv = 1.f / den;

  float* o = p.out + (size_t)s * 105;
  float pos[4][3], coef[4][9], cov[4][9];
  for (int e = 0; e < 3; ++e) {
    for (int d = 0; d < 3; ++d) pos[e][d]  = hd[e][d] + p.ent_bpos[e * 3 + d];
    for (int c = 0; c < 9; ++c) coef[e][c] = hd[e][3 + c] + p.ent_bc[e * 9 + c];
    for (int c = 0; c < 9; ++c) cov[e][c]  = softplusf(hd[e][12 + c] + p.ent_bv[e * 9 + c]);
  }
  for (int d = 0; d < 3; ++d) pos[3][d]  = agg[d] * inv + p.b_bpos[d];
  for (int c = 0; c < 9; ++c) coef[3][c] = agg[3 + c] * inv + p.b_bc[c];
  for (int c = 0; c < 9; ++c) cov[3][c]  = softplusf(agg[12 + c] * inv + p.b_bv[c]);
  for (int i = 0; i < 4; ++i) {
    float x = pos[i][0], y = pos[i][1], z = pos[i][2];
    for (int c = 0; c < 9; ++c) o[i * 24 + c]     = coef[i][c];
    for (int c = 0; c < 9; ++c) o[i * 24 + 9 + c] = cov[i][c];
    o[i * 24 + 18] = (4096.f - x) * 1e-3f;
    o[i * 24 + 19] = (4096.f + x) * 1e-3f;
    o[i * 24 + 20] = (5120.f - y) * 1e-3f;
    o[i * 24 + 21] = (5120.f + y) * 1e-3f;
    o[i * 24 + 22] = z * 1e-3f;
    o[i * 24 + 23] = (2044.f - z) * 1e-3f;
  }
  const int iu[6] = {0, 0, 0, 1, 1, 2}, ju[6] = {1, 2, 3, 2, 3, 3};
  for (int q = 0; q < 6; ++q) {
    int i = iu[q], j = ju[q];
    float d2 = 0.f, cd = 0.f;
    for (int d = 0; d < 3; ++d) { float df = pos[i][d] - pos[j][d]; d2 = fmaf(df, df, d2); }
    for (int c = 0; c < 9; ++c) cd = fmaf(coef[i][c], coef[j][c], cd);
    o[96 + q] = expf(-2.f * d2) * cd;
  }
  for (int d = 0; d < 3; ++d) {
    float ga = p.gs_b[d];
    for (int k = 0; k < 10; ++k)
      ga = fmaf(p.tokens[(size_t)s * 100 + 90 + k], p.gs_W[k * 3 + d], ga);
    o[102 + d] = ga;
  }
}

extern "C" void kernel_launch(void* const* d_in, const int* in_sizes, int n_in,
                              void* d_out, int out_size) {
  pack_kernel<<<512, 256>>>(
      (const float*)d_in[3],  (const float*)d_in[13],
      (const float*)d_in[1],  (const float*)d_in[2],
      (const float*)d_in[11], (const float*)d_in[12],
      (const float*)d_in[5],  (const float*)d_in[7],  (const float*)d_in[9],
      (const float*)d_in[17], (const float*)d_in[19], (const float*)d_in[21],
      (const float*)d_in[15]);

  int B = in_sizes[0] / 100;

  PM pm;
  pm.tokens = (const float*)d_in[0];
  pm.ent_b2 = (const float*)d_in[4];
  pm.pad_b2 = (const float*)d_in[14];
  cudaFuncSetAttribute(spectral_mma_kernel, cudaFuncAttributeMaxDynamicSharedMemorySize, SMEM_SZ);
  dim3 grid(B / 128, 18);
  spectral_mma_kernel<<<grid, NTH, SMEM_SZ>>>(pm);

  PE pe;
  pe.tokens = (const float*)d_in[0];
  pe.ent_bpos = (const float*)d_in[6];
  pe.ent_bc = (const float*)d_in[8];
  pe.ent_bv = (const float*)d_in[10];
  pe.b_bpos = (const float*)d_in[18];
  pe.b_bc = (const float*)d_in[20];
  pe.b_bv = (const float*)d_in[22];
  pe.gs_W = (const float*)d_in[23];
  pe.gs_b = (const float*)d_in[24];
  pe.out = (float*)d_out;
  epilogue_kernel<<<(B + 127) / 128, 128>>>(pe, B);
}

// round 9
// speedup vs baseline: 1.0944x; 1.0944x over previous
#include <cuda_runtime.h>
#include <cuda_fp16.h>
#include <math.h>
#include <stdint.h>

// ---------------- packed fp16 weights ----------------
// g_w2: [m4][nh2][kc32][n256][k16] = 1,048,576 halves (2MB)   (k16 chunks)
// g_w1: [m4][n512][k16]  (k10 = b1) = 32,768 halves
// g_hd: [m4][n32][k512]  (n: 0-2 pos, 3-11 coef, 12-20 cov, 21 attn, 22-31 zero)
__device__ __align__(16) __half g_w2[1048576];
__device__ __align__(16) __half g_w1[32768];
__device__ __align__(16) __half g_hd[65536];
// head partials: [g*2+nh (18)][sample (32768)][22] f32
__device__ float g_part[18 * 32768 * 22];

struct PM {
  const float *tokens;
  const float *ent_b2, *pad_b2;
};
struct PE {
  const float *tokens;
  const float *ent_bpos, *ent_bc, *ent_bv;
  const float *b_bpos, *b_bc, *b_bv;
  const float *gs_W, *gs_b;
  float *out;
};

__global__ void pack_kernel(const float* eW2, const float* pW2,
                            const float* eW1, const float* eb1,
                            const float* pW1, const float* pb1,
                            const float* eWpos, const float* eWc, const float* eWv,
                            const float* bWpos, const float* bWc, const float* bWv,
                            const float* attnW) {
  int tid = blockIdx.x * blockDim.x + threadIdx.x;
  int NT = gridDim.x * blockDim.x;
  for (int idx = tid; idx < 4 * 512 * 512; idx += NT) {
    int m = idx >> 18, r = idx & 262143, k = r >> 9, n = r & 511;
    float v = (m < 3) ? eW2[m * 262144 + k * 512 + n] : pW2[k * 512 + n];
    // [m][nh][kc k>>4][n 256][k&15]
    int dst = ((((m * 2 + (n >> 8)) * 32 + (k >> 4)) * 256) + (n & 255)) * 16 + (k & 15);
    g_w2[dst] = __float2half(v);
  }
  for (int idx = tid; idx < 4 * 512 * 16; idx += NT) {
    int m = idx >> 13, r = idx & 8191, n = r >> 4, k = r & 15;
    float v = 0.f;
    if (k < 10)       v = (m < 3) ? eW1[m * 5120 + k * 512 + n] : pW1[k * 512 + n];
    else if (k == 10) v = (m < 3) ? eb1[m * 512 + n] : pb1[n];
    g_w1[(m * 512 + n) * 16 + k] = __float2half(v);
  }
  for (int idx = tid; idx < 4 * 32 * 512; idx += NT) {
    int m = idx >> 14, r = idx & 16383, n = r >> 9, k = r & 511;
    float v = 0.f;
    if (m < 3) {
      if (n < 3)       v = eWpos[m * 1536 + k * 3 + n];
      else if (n < 12) v = eWc[m * 4608 + k * 9 + (n - 3)];
      else if (n < 21) v = eWv[m * 4608 + k * 9 + (n - 12)];
    } else {
      if (n < 3)       v = bWpos[k * 3 + n];
      else if (n < 12) v = bWc[k * 9 + (n - 3)];
      else if (n < 21) v = bWv[k * 9 + (n - 12)];
      else if (n == 21) v = attnW[k];
    }
    g_hd[(m * 32 + n) * 512 + k] = __float2half(v);
  }
}

// ---------------- mma helpers ----------------
__device__ __forceinline__ void ldsm4(uint32_t a, uint32_t& r0, uint32_t& r1,
                                      uint32_t& r2, uint32_t& r3) {
  asm volatile("ldmatrix.sync.aligned.m8n8.x4.shared.b16 {%0,%1,%2,%3}, [%4];"
               : "=r"(r0), "=r"(r1), "=r"(r2), "=r"(r3) : "r"(a));
}
__device__ __forceinline__ void mma16816(float* c, uint32_t a0, uint32_t a1,
                                         uint32_t a2, uint32_t a3,
                                         uint32_t b0, uint32_t b1) {
  asm volatile(
      "mma.sync.aligned.m16n8k16.row.col.f32.f16.f16.f32 "
      "{%0,%1,%2,%3},{%4,%5,%6,%7},{%8,%9},{%0,%1,%2,%3};"
      : "+f"(c[0]), "+f"(c[1]), "+f"(c[2]), "+f"(c[3])
      : "r"(a0), "r"(a1), "r"(a2), "r"(a3), "r"(b0), "r"(b1));
}
#define CP16(dst, src) asm volatile("cp.async.ca.shared.global [%0], [%1], 16;" :: "r"(dst), "l"(src))
#define CPCOMMIT() asm volatile("cp.async.commit_group;" ::: "memory")
#define CPWAIT2() asm volatile("cp.async.wait_group 2;" ::: "memory")

// ---------------- swizzled addressing ----------------
// A tile: 64 rows x 1024B (512 halves), bank-swizzled
__device__ __forceinline__ int swA(int row, int kbyte) {
  return (row * 1024 + kbyte) ^ ((row & 7) << 4);
}
// B stage: 256 n-rows x 32B (16 halves), bank-swizzled
__device__ __forceinline__ int swB(int n, int kbyte) {
  return (n * 32 + kbyte) ^ (((n >> 2) & 1) << 4);
}

// ---------------- smem layout (bytes) ----------------
#define NTH 256
static constexpr int OF_A  = 0;        // 65,536
static constexpr int OF_R  = 65536;    // ring: 4 x 8192 = 32,768
                                       // overlays: W1T (512x48B=24,576) + x-tile at +24576 (2048) [prologue]
                                       //           heads B (32x528B=16,896) + s_part at +17408 (6,144) [tail]
static constexpr int OF_XT = OF_R + 24576;
static constexpr int OF_HB = OF_R;
static constexpr int OF_P  = OF_R + 17408;
static constexpr int SMEM_SZ = 98304;  // 96 KB -> 2 CTAs/SM

__device__ __forceinline__ float softplusf(float x) { return (x > 20.f) ? x : log1pf(expf(x)); }

__global__ void __launch_bounds__(NTH, 2) spectral_mma_kernel(PM p) {
  extern __shared__ __align__(128) unsigned char sm[];
  const uint32_t smb = (uint32_t)__cvta_generic_to_shared(sm);
  const int t = threadIdx.x, wid = t >> 5, lane = t & 31;
  const int g = blockIdx.y >> 1, nh = blockIdx.y & 1;
  const int m = (g < 3) ? g : 3;
  const int s0 = blockIdx.x * 64;
  const int mw = wid & 1, nw = wid >> 1;                // 2 M-warps x 4 N-warps
  const int ag_r = ((lane >> 3) & 1) * 8 + (lane & 7);  // A ldsm: row offset
  const int ag_k = ((lane >> 4) & 1) * 8;               // A ldsm: k offset
  const int bg_n = ((lane >> 4) & 1) * 8 + (lane & 7);  // B ldsm: n offset
  const int bg_k = ((lane >> 3) & 1) * 8;               // B ldsm: k offset
  const int lr = lane >> 2, lc2 = (lane & 3) * 2;       // C frag mapping

  // ---- prologue: build x-tile + park W1T in ring ----
  for (int i = t; i < 64 * 16; i += NTH) {
    int s = i >> 4, k = i & 15;
    float v = (k < 10) ? p.tokens[(size_t)(s0 + s) * 100 + g * 10 + k] : (k == 10 ? 1.f : 0.f);
    *(__half*)(sm + OF_XT + s * 32 + k * 2) = __float2half(v);
  }
  for (int u = t; u < 1024; u += NTH)    // W1T: 512 rows x 32B data, 48B stride
    *(uint4*)(sm + OF_R + (u >> 1) * 48 + (u & 1) * 16) =
        *(const uint4*)((const char*)g_w1 + m * 16384 + u * 16);
  __syncthreads();

  // ---- phase A: h1 = relu(x @ W1T) -> swizzled A-tile, two 256-col passes ----
  {
    uint32_t xa[2][4];
    ldsm4(smb + OF_XT + (mw * 32 + ag_r) * 32 + ag_k * 2, xa[0][0], xa[0][1], xa[0][2], xa[0][3]);
    ldsm4(smb + OF_XT + (mw * 32 + 16 + ag_r) * 32 + ag_k * 2, xa[1][0], xa[1][1], xa[1][2], xa[1][3]);
#pragma unroll
    for (int pss = 0; pss < 2; ++pss) {
#pragma unroll
      for (int pq = 0; pq < 4; ++pq) {
        uint32_t b[4];
        int nr = pss * 256 + nw * 64 + pq * 16 + bg_n;
        ldsm4(smb + OF_R + nr * 48 + bg_k * 2, b[0], b[1], b[2], b[3]);
        float pa[2][2][4];
#pragma unroll
        for (int mt = 0; mt < 2; ++mt)
#pragma unroll
          for (int tn = 0; tn < 2; ++tn) {
#pragma unroll
            for (int i = 0; i < 4; ++i) pa[mt][tn][i] = 0.f;
            mma16816(pa[mt][tn], xa[mt][0], xa[mt][1], xa[mt][2], xa[mt][3],
                     b[tn * 2], b[tn * 2 + 1]);
          }
#pragma unroll
        for (int mt = 0; mt < 2; ++mt)
#pragma unroll
          for (int tn = 0; tn < 2; ++tn) {
            int col = pss * 256 + nw * 64 + pq * 16 + tn * 8 + lc2;
            int row0 = mw * 32 + mt * 16 + lr;
            *(__half2*)(sm + OF_A + swA(row0, col * 2)) =
                __floats2half2_rn(fmaxf(pa[mt][tn][0], 0.f), fmaxf(pa[mt][tn][1], 0.f));
            *(__half2*)(sm + OF_A + swA(row0 + 8, col * 2)) =
                __floats2half2_rn(fmaxf(pa[mt][tn][2], 0.f), fmaxf(pa[mt][tn][3], 0.f));
          }
      }
    }
  }
  __syncthreads();   // h1 complete; ring (W1/x) now free

  // ---- cp.async prologue: k16 chunks 0..2 into stages 0..2 ----
  const char* w2base = (const char*)g_w2 + (size_t)(m * 2 + nh) * 262144;  // 32 chunks x 8192B
#pragma unroll
  for (int st = 0; st < 3; ++st) {
    const char* src = w2base + st * 8192;
    for (int u = t; u < 512; u += NTH)
      CP16(smb + OF_R + st * 8192 + swB(u >> 1, (u & 1) * 16), src + u * 16);
    CPCOMMIT();
  }

  float acc[2][8][4];
#pragma unroll
  for (int mt = 0; mt < 2; ++mt)
#pragma unroll
    for (int nt = 0; nt < 8; ++nt)
#pragma unroll
      for (int i = 0; i < 4; ++i) acc[mt][nt][i] = 0.f;

  // ---- GEMM1 mainloop: 32 k16 chunks, 4-stage ring, wait_group 2 ----
  for (int kc = 0; kc < 32; ++kc) {
    CPWAIT2();
    __syncthreads();
    if (kc < 29) {
      int st = (kc + 3) & 3;
      const char* src = w2base + (kc + 3) * 8192;
      for (int u = t; u < 512; u += NTH)
        CP16(smb + OF_R + st * 8192 + swB(u >> 1, (u & 1) * 16), src + u * 16);
    }
    CPCOMMIT();
    uint32_t bo = smb + OF_R + (kc & 3) * 8192;
    int ak = kc * 16;
    uint32_t A0[4], A1[4];
    ldsm4(smb + OF_A + swA(mw * 32 + ag_r, (ak + ag_k) * 2), A0[0], A0[1], A0[2], A0[3]);
    ldsm4(smb + OF_A + swA(mw * 32 + 16 + ag_r, (ak + ag_k) * 2), A1[0], A1[1], A1[2], A1[3]);
#pragma unroll
    for (int pq = 0; pq < 4; ++pq) {
      uint32_t b[4];
      ldsm4(bo + swB(nw * 64 + pq * 16 + bg_n, bg_k * 2), b[0], b[1], b[2], b[3]);
      mma16816(acc[0][pq * 2],     A0[0], A0[1], A0[2], A0[3], b[0], b[1]);
      mma16816(acc[0][pq * 2 + 1], A0[0], A0[1], A0[2], A0[3], b[2], b[3]);
      mma16816(acc[1][pq * 2],     A1[0], A1[1], A1[2], A1[3], b[0], b[1]);
      mma16816(acc[1][pq * 2 + 1], A1[0], A1[1], A1[2], A1[3], b[2], b[3]);
    }
  }
  __syncthreads();   // all ring reads done

  // ---- h2 (bias+relu) -> A-tile cols 0..255 (overwrite) ----
  {
    const float* b2 = (g < 3) ? (p.ent_b2 + m * 512) : p.pad_b2;
#pragma unroll
    for (int mt = 0; mt < 2; ++mt)
#pragma unroll
      for (int nt = 0; nt < 8; ++nt) {
        int lcol = nw * 64 + nt * 8 + lc2;
        float bb0 = __ldg(b2 + nh * 256 + lcol), bb1 = __ldg(b2 + nh * 256 + lcol + 1);
        int row0 = mw * 32 + mt * 16 + lr;
        *(__half2*)(sm + OF_A + swA(row0, lcol * 2)) =
            __floats2half2_rn(fmaxf(acc[mt][nt][0] + bb0, 0.f), fmaxf(acc[mt][nt][1] + bb1, 0.f));
        *(__half2*)(sm + OF_A + swA(row0 + 8, lcol * 2)) =
            __floats2half2_rn(fmaxf(acc[mt][nt][2] + bb0, 0.f), fmaxf(acc[mt][nt][3] + bb1, 0.f));
      }
  }
  // ---- copy Whd k-half slice (32 n x 256 k) into ring, stride 528B; zero s_part ----
  for (int u = t; u < 1024; u += NTH)
    *(uint4*)(sm + OF_HB + (u >> 5) * 528 + (u & 31) * 16) =
        *(const uint4*)(g_hd + (size_t)(m * 32 + (u >> 5)) * 512 + nh * 256 + (u & 31) * 8);
  for (int i = t; i < 64 * 24; i += NTH) ((float*)(sm + OF_P))[i] = 0.f;
  __syncthreads();

  // ---- heads GEMM: warp = (row strip mw x2) x (k-slice nw of 64), n=24 ----
  {
    float hacc[2][3][4];
#pragma unroll
    for (int mt = 0; mt < 2; ++mt)
#pragma unroll
      for (int nt = 0; nt < 3; ++nt)
#pragma unroll
        for (int i = 0; i < 4; ++i) hacc[mt][nt][i] = 0.f;
#pragma unroll
    for (int q = 0; q < 4; ++q) {
      int koff = nw * 64 + q * 16;
      uint32_t A0[4], A1[4], b0[4], b1[4];
      ldsm4(smb + OF_A + swA(mw * 32 + ag_r, (koff + ag_k) * 2), A0[0], A0[1], A0[2], A0[3]);
      ldsm4(smb + OF_A + swA(mw * 32 + 16 + ag_r, (koff + ag_k) * 2), A1[0], A1[1], A1[2], A1[3]);
      ldsm4(smb + OF_HB + bg_n * 528 + (koff + bg_k) * 2, b0[0], b0[1], b0[2], b0[3]);
      ldsm4(smb + OF_HB + (16 + bg_n) * 528 + (koff + bg_k) * 2, b1[0], b1[1], b1[2], b1[3]);
      mma16816(hacc[0][0], A0[0], A0[1], A0[2], A0[3], b0[0], b0[1]);
      mma16816(hacc[0][1], A0[0], A0[1], A0[2], A0[3], b0[2], b0[3]);
      mma16816(hacc[0][2], A0[0], A0[1], A0[2], A0[3], b1[0], b1[1]);
      mma16816(hacc[1][0], A1[0], A1[1], A1[2], A1[3], b0[0], b0[1]);
      mma16816(hacc[1][1], A1[0], A1[1], A1[2], A1[3], b0[2], b0[3]);
      mma16816(hacc[1][2], A1[0], A1[1], A1[2], A1[3], b1[0], b1[1]);
    }
    float* sp = (float*)(sm + OF_P);
#pragma unroll
    for (int mt = 0; mt < 2; ++mt)
#pragma unroll
      for (int nt = 0; nt < 3; ++nt) {
        int row0 = mw * 32 + mt * 16 + lr, col = nt * 8 + lc2;
        atomicAdd(sp + row0 * 24 + col,           hacc[mt][nt][0]);
        atomicAdd(sp + row0 * 24 + col + 1,       hacc[mt][nt][1]);
        atomicAdd(sp + (row0 + 8) * 24 + col,     hacc[mt][nt][2]);
        atomicAdd(sp + (row0 + 8) * 24 + col + 1, hacc[mt][nt][3]);
      }
  }
  __syncthreads();

  for (int i = t; i < 64 * 22; i += NTH) {
    int s = i / 22, c = i - s * 22;
    g_part[((size_t)(g * 2 + nh) * 32768 + s0 + s) * 22 + c] = ((float*)(sm + OF_P))[s * 24 + c];
  }
}

__global__ void epilogue_kernel(PE p, int B) {
  int s = blockIdx.x * blockDim.x + threadIdx.x;
  if (s >= B) return;
  float hd[9][22];
#pragma unroll
  for (int q = 0; q < 9; ++q) {
    const float* p0 = g_part + ((size_t)(q * 2) * 32768 + s) * 22;
    const float* p1 = g_part + ((size_t)(q * 2 + 1) * 32768 + s) * 22;
#pragma unroll
    for (int c = 0; c < 22; ++c) hd[q][c] = p0[c] + p1[c];
  }
  float mx = -1e30f;
#pragma unroll
  for (int q = 3; q < 9; ++q) mx = fmaxf(mx, hd[q][21]);
  float den = 0.f, agg[21];
#pragma unroll
  for (int c = 0; c < 21; ++c) agg[c] = 0.f;
#pragma unroll
  for (int q = 3; q < 9; ++q) {
    float w = expf(hd[q][21] - mx);
    den += w;
#pragma unroll
    for (int c = 0; c < 21; ++c) agg[c] = fmaf(w, hd[q][c], agg[c]);
  }
  float inv = 1.f / den;

  float* o = p.out + (size_t)s * 105;
  float pos[4][3], coef[4][9], cov[4][9];
  for (int e = 0; e < 3; ++e) {
    for (int d = 0; d < 3; ++d) pos[e][d]  = hd[e][d] + p.ent_bpos[e * 3 + d];
    for (int c = 0; c < 9; ++c) coef[e][c] = hd[e][3 + c] + p.ent_bc[e * 9 + c];
    for (int c = 0; c < 9; ++c) cov[e][c]  = softplusf(hd[e][12 + c] + p.ent_bv[e * 9 + c]);
  }
  for (int d = 0; d < 3; ++d) pos[3][d]  = agg[d] * inv + p.b_bpos[d];
  for (int c = 0; c < 9; ++c) coef[3][c] = agg[3 + c] * inv + p.b_bc[c];
  for (int c = 0; c < 9; ++c) cov[3][c]  = softplusf(agg[12 + c] * inv + p.b_bv[c]);
  for (int i = 0; i < 4; ++i) {
    float x = pos[i][0], y = pos[i][1], z = pos[i][2];
    for (int c = 0; c < 9; ++c) o[i * 24 + c]     = coef[i][c];
    for (int c = 0; c < 9; ++c) o[i * 24 + 9 + c] = cov[i][c];
    o[i * 24 + 18] = (4096.f - x) * 1e-3f;
    o[i * 24 + 19] = (4096.f + x) * 1e-3f;
    o[i * 24 + 20] = (5120.f - y) * 1e-3f;
    o[i * 24 + 21] = (5120.f + y) * 1e-3f;
    o[i * 24 + 22] = z * 1e-3f;
    o[i * 24 + 23] = (2044.f - z) * 1e-3f;
  }
  const int iu[6] = {0, 0, 0, 1, 1, 2}, ju[6] = {1, 2, 3, 2, 3, 3};
  for (int q = 0; q < 6; ++q) {
    int i = iu[q], j = ju[q];
    float d2 = 0.f, cd = 0.f;
    for (int d = 0; d < 3; ++d) { float df = pos[i][d] - pos[j][d]; d2 = fmaf(df, df, d2); }
    for (int c = 0; c < 9; ++c) cd = fmaf(coef[i][c], coef[j][c], cd);
    o[96 + q] = expf(-2.f * d2) * cd;
  }
  for (int d = 0; d < 3; ++d) {
    float ga = p.gs_b[d];
    for (int k = 0; k < 10; ++k)
      ga = fmaf(p.tokens[(size_t)s * 100 + 90 + k], p.gs_W[k * 3 + d], ga);
    o[102 + d] = ga;
  }
}

extern "C" void kernel_launch(void* const* d_in, const int* in_sizes, int n_in,
                              void* d_out, int out_size) {
  pack_kernel<<<512, 256>>>(
      (const float*)d_in[3],  (const float*)d_in[13],
      (const float*)d_in[1],  (const float*)d_in[2],
      (const float*)d_in[11], (const float*)d_in[12],
      (const float*)d_in[5],  (const float*)d_in[7],  (const float*)d_in[9],
      (const float*)d_in[17], (const float*)d_in[19], (const float*)d_in[21],
      (const float*)d_in[15]);

  int B = in_sizes[0] / 100;

  PM pm;
  pm.tokens = (const float*)d_in[0];
  pm.ent_b2 = (const float*)d_in[4];
  pm.pad_b2 = (const float*)d_in[14];
  cudaFuncSetAttribute(spectral_mma_kernel, cudaFuncAttributeMaxDynamicSharedMemorySize, SMEM_SZ);
  dim3 grid(B / 64, 18);
  spectral_mma_kernel<<<grid, NTH, SMEM_SZ>>>(pm);

  PE pe;
  pe.tokens = (const float*)d_in[0];
  pe.ent_bpos = (const float*)d_in[6];
  pe.ent_bc = (const float*)d_in[8];
  pe.ent_bv = (const float*)d_in[10];
  pe.b_bpos = (const float*)d_in[18];
  pe.b_bc = (const float*)d_in[20];
  pe.b_bv = (const float*)d_in[22];
  pe.gs_W = (const float*)d_in[23];
  pe.gs_b = (const float*)d_in[24];
  pe.out = (float*)d_out;
  epilogue_kernel<<<(B + 127) / 128, 128>>>(pe, B);
}